// round 1
// baseline (speedup 1.0000x reference)
#include <cuda_runtime.h>

// Problem constants
constexpr int BATCH = 4;
constexpr int SEQ   = 2048;
constexpr int HID   = 1024;
constexpr int NHEAD = 16;
constexpr int HDIM  = 64;
constexpr int MROWS = BATCH * SEQ;              // 8192
constexpr long long OUT_ELEMS   = (long long)BATCH * SEQ * HID;            // 8,388,608
constexpr long long PROBS_ELEMS = (long long)BATCH * NHEAD * SEQ * SEQ;    // 268,435,456

// Scratch (static device arrays; no allocation allowed)
__device__ float g_q[BATCH * NHEAD * SEQ * HDIM];   // [b,h,s,d]
__device__ float g_k[BATCH * NHEAD * SEQ * HDIM];
__device__ float g_v[BATCH * NHEAD * SEQ * HDIM];
__device__ float g_ctx[BATCH * SEQ * HID];          // [b,s,h*64+d]

// ---------------------------------------------------------------------------
// Fused QKV projection: C = X @ W^T + b, written head-major [b,h,s,d].
// NT GEMM, M=8192, N=1024, K=1024. BM=BN=128, BK=8, 16x16 threads, 8x8 micro.
// blockIdx.z in {0,1,2} selects Q/K/V.
// ---------------------------------------------------------------------------
__global__ __launch_bounds__(256) void qkv_gemm(
    const float* __restrict__ X,
    const float* __restrict__ Wq, const float* __restrict__ bq,
    const float* __restrict__ Wk, const float* __restrict__ bk,
    const float* __restrict__ Wv, const float* __restrict__ bv)
{
    const float* W; const float* bias; float* dst;
    if (blockIdx.z == 0)      { W = Wq; bias = bq; dst = g_q; }
    else if (blockIdx.z == 1) { W = Wk; bias = bk; dst = g_k; }
    else                      { W = Wv; bias = bv; dst = g_v; }

    __shared__ float As[8][128];
    __shared__ float Ws[8][128];

    const int tx = threadIdx.x, ty = threadIdx.y;
    const int tid = ty * 16 + tx;
    const int m0 = blockIdx.y * 128;
    const int n0 = blockIdx.x * 128;

    float acc[8][8];
#pragma unroll
    for (int i = 0; i < 8; i++)
#pragma unroll
        for (int j = 0; j < 8; j++) acc[i][j] = 0.f;

    const int lrow = tid >> 1;
    const int lkq  = (tid & 1) * 4;

    for (int k0 = 0; k0 < HID; k0 += 8) {
        float4 va = *(const float4*)(X + (long long)(m0 + lrow) * HID + k0 + lkq);
        As[lkq + 0][lrow] = va.x; As[lkq + 1][lrow] = va.y;
        As[lkq + 2][lrow] = va.z; As[lkq + 3][lrow] = va.w;
        float4 vw = *(const float4*)(W + (long long)(n0 + lrow) * HID + k0 + lkq);
        Ws[lkq + 0][lrow] = vw.x; Ws[lkq + 1][lrow] = vw.y;
        Ws[lkq + 2][lrow] = vw.z; Ws[lkq + 3][lrow] = vw.w;
        __syncthreads();

#pragma unroll
        for (int kk = 0; kk < 8; kk++) {
            float a[8], w[8];
            *(float4*)(a)     = *(const float4*)&As[kk][ty * 8];
            *(float4*)(a + 4) = *(const float4*)&As[kk][ty * 8 + 4];
            *(float4*)(w)     = *(const float4*)&Ws[kk][tx * 8];
            *(float4*)(w + 4) = *(const float4*)&Ws[kk][tx * 8 + 4];
#pragma unroll
            for (int i = 0; i < 8; i++)
#pragma unroll
                for (int j = 0; j < 8; j++)
                    acc[i][j] = fmaf(a[i], w[j], acc[i][j]);
        }
        __syncthreads();
    }

#pragma unroll
    for (int i = 0; i < 8; i++) {
        const int m = m0 + ty * 8 + i;
        const int b = m / SEQ, s = m % SEQ;
#pragma unroll
        for (int j = 0; j < 8; j++) {
            const int n = n0 + tx * 8 + j;
            const int h = n >> 6, d = n & 63;
            dst[(((long long)(b * NHEAD + h)) * SEQ + s) * HDIM + d] = acc[i][j] + bias[n];
        }
    }
}

// ---------------------------------------------------------------------------
// Scores: S[bh, i, j] = Q[bh,i,:] . K[bh,j,:]  (NT GEMM, M=N=2048, K=64)
// Written directly into the probs region of d_out.
// ---------------------------------------------------------------------------
__global__ __launch_bounds__(256) void scores_gemm(float* __restrict__ probs)
{
    const int bh = blockIdx.z;
    const float* Q = g_q + (long long)bh * SEQ * HDIM;
    const float* Kd = g_k + (long long)bh * SEQ * HDIM;
    float* C = probs + (long long)bh * SEQ * SEQ;

    __shared__ float As[8][128];
    __shared__ float Ws[8][128];

    const int tx = threadIdx.x, ty = threadIdx.y;
    const int tid = ty * 16 + tx;
    const int m0 = blockIdx.y * 128;
    const int n0 = blockIdx.x * 128;

    float acc[8][8];
#pragma unroll
    for (int i = 0; i < 8; i++)
#pragma unroll
        for (int j = 0; j < 8; j++) acc[i][j] = 0.f;

    const int lrow = tid >> 1;
    const int lkq  = (tid & 1) * 4;

    for (int k0 = 0; k0 < HDIM; k0 += 8) {
        float4 va = *(const float4*)(Q + (long long)(m0 + lrow) * HDIM + k0 + lkq);
        As[lkq + 0][lrow] = va.x; As[lkq + 1][lrow] = va.y;
        As[lkq + 2][lrow] = va.z; As[lkq + 3][lrow] = va.w;
        float4 vw = *(const float4*)(Kd + (long long)(n0 + lrow) * HDIM + k0 + lkq);
        Ws[lkq + 0][lrow] = vw.x; Ws[lkq + 1][lrow] = vw.y;
        Ws[lkq + 2][lrow] = vw.z; Ws[lkq + 3][lrow] = vw.w;
        __syncthreads();

#pragma unroll
        for (int kk = 0; kk < 8; kk++) {
            float a[8], w[8];
            *(float4*)(a)     = *(const float4*)&As[kk][ty * 8];
            *(float4*)(a + 4) = *(const float4*)&As[kk][ty * 8 + 4];
            *(float4*)(w)     = *(const float4*)&Ws[kk][tx * 8];
            *(float4*)(w + 4) = *(const float4*)&Ws[kk][tx * 8 + 4];
#pragma unroll
            for (int i = 0; i < 8; i++)
#pragma unroll
                for (int j = 0; j < 8; j++)
                    acc[i][j] = fmaf(a[i], w[j], acc[i][j]);
        }
        __syncthreads();
    }

#pragma unroll
    for (int i = 0; i < 8; i++) {
        const long long m = m0 + ty * 8 + i;
#pragma unroll
        for (int j = 0; j < 4; j++) { }  // (kept unrolled store below)
        float4 s0, s1;
        s0.x = acc[i][0]; s0.y = acc[i][1]; s0.z = acc[i][2]; s0.w = acc[i][3];
        s1.x = acc[i][4]; s1.y = acc[i][5]; s1.z = acc[i][6]; s1.w = acc[i][7];
        *(float4*)(C + m * SEQ + n0 + tx * 8)     = s0;
        *(float4*)(C + m * SEQ + n0 + tx * 8 + 4) = s1;
    }
}

// ---------------------------------------------------------------------------
// Row softmax over 2048 elems, one block per row, 8 elems/thread in registers.
// ---------------------------------------------------------------------------
__global__ __launch_bounds__(256) void softmax_rows(float* __restrict__ probs)
{
    const long long row = blockIdx.x;
    float* p = probs + row * (long long)SEQ;
    const int t = threadIdx.x;

    float4 v0 = *(const float4*)(p + t * 8);
    float4 v1 = *(const float4*)(p + t * 8 + 4);

    float vmax = fmaxf(fmaxf(fmaxf(v0.x, v0.y), fmaxf(v0.z, v0.w)),
                       fmaxf(fmaxf(v1.x, v1.y), fmaxf(v1.z, v1.w)));
    __shared__ float red[8];
#pragma unroll
    for (int o = 16; o > 0; o >>= 1)
        vmax = fmaxf(vmax, __shfl_xor_sync(0xffffffffu, vmax, o));
    if ((t & 31) == 0) red[t >> 5] = vmax;
    __syncthreads();
    vmax = red[0];
#pragma unroll
    for (int i = 1; i < 8; i++) vmax = fmaxf(vmax, red[i]);
    __syncthreads();

    v0.x = __expf(v0.x - vmax); v0.y = __expf(v0.y - vmax);
    v0.z = __expf(v0.z - vmax); v0.w = __expf(v0.w - vmax);
    v1.x = __expf(v1.x - vmax); v1.y = __expf(v1.y - vmax);
    v1.z = __expf(v1.z - vmax); v1.w = __expf(v1.w - vmax);

    float sum = v0.x + v0.y + v0.z + v0.w + v1.x + v1.y + v1.z + v1.w;
#pragma unroll
    for (int o = 16; o > 0; o >>= 1)
        sum += __shfl_xor_sync(0xffffffffu, sum, o);
    if ((t & 31) == 0) red[t >> 5] = sum;
    __syncthreads();
    sum = red[0];
#pragma unroll
    for (int i = 1; i < 8; i++) sum += red[i];

    const float inv = 1.0f / sum;
    v0.x *= inv; v0.y *= inv; v0.z *= inv; v0.w *= inv;
    v1.x *= inv; v1.y *= inv; v1.z *= inv; v1.w *= inv;
    *(float4*)(p + t * 8)     = v0;
    *(float4*)(p + t * 8 + 4) = v1;
}

// ---------------------------------------------------------------------------
// Context: ctx[bh, i, :] = P[bh, i, :] @ V[bh, :, :]   (NN GEMM, M=2048, N=64,
// K=2048). BM=128, BN=64, BK=16, 16x16 threads, 8x4 micro.
// Output written as [b, s, h*64 + d].
// ---------------------------------------------------------------------------
__global__ __launch_bounds__(256) void ctx_gemm(const float* __restrict__ probs)
{
    const int bh = blockIdx.z;
    const int b = bh / NHEAD, h = bh % NHEAD;
    const float* A  = probs + (long long)bh * SEQ * SEQ;   // [SEQ, SEQ]
    const float* Vm = g_v  + (long long)bh * SEQ * HDIM;   // [SEQ, 64]

    __shared__ float As[16][128];
    __shared__ float Bs[16][64];

    const int tx = threadIdx.x, ty = threadIdx.y;
    const int tid = ty * 16 + tx;
    const int m0 = blockIdx.y * 128;

    float acc[8][4];
#pragma unroll
    for (int i = 0; i < 8; i++)
#pragma unroll
        for (int j = 0; j < 4; j++) acc[i][j] = 0.f;

    const int lrow = tid >> 1;          // 0..127
    const int lkq  = (tid & 1) * 8;     // 0 or 8
    const int bkr  = tid >> 4;          // 0..15
    const int bnc  = (tid & 15) * 4;    // 0..60

    for (int k0 = 0; k0 < SEQ; k0 += 16) {
        float4 a0 = *(const float4*)(A + (long long)(m0 + lrow) * SEQ + k0 + lkq);
        float4 a1 = *(const float4*)(A + (long long)(m0 + lrow) * SEQ + k0 + lkq + 4);
        As[lkq + 0][lrow] = a0.x; As[lkq + 1][lrow] = a0.y;
        As[lkq + 2][lrow] = a0.z; As[lkq + 3][lrow] = a0.w;
        As[lkq + 4][lrow] = a1.x; As[lkq + 5][lrow] = a1.y;
        As[lkq + 6][lrow] = a1.z; As[lkq + 7][lrow] = a1.w;
        *(float4*)&Bs[bkr][bnc] = *(const float4*)(Vm + (long long)(k0 + bkr) * HDIM + bnc);
        __syncthreads();

#pragma unroll
        for (int kk = 0; kk < 16; kk++) {
            float a[8], w[4];
            *(float4*)(a)     = *(const float4*)&As[kk][ty * 8];
            *(float4*)(a + 4) = *(const float4*)&As[kk][ty * 8 + 4];
            *(float4*)(w)     = *(const float4*)&Bs[kk][tx * 4];
#pragma unroll
            for (int i = 0; i < 8; i++)
#pragma unroll
                for (int j = 0; j < 4; j++)
                    acc[i][j] = fmaf(a[i], w[j], acc[i][j]);
        }
        __syncthreads();
    }

#pragma unroll
    for (int i = 0; i < 8; i++) {
        const int s = m0 + ty * 8 + i;
        float4 st;
        st.x = acc[i][0]; st.y = acc[i][1]; st.z = acc[i][2]; st.w = acc[i][3];
        *(float4*)(g_ctx + ((long long)(b * SEQ + s)) * HID + h * HDIM + tx * 4) = st;
    }
}

// ---------------------------------------------------------------------------
// Output projection + residual: out = ctx @ Wo^T + bo + hidden.
// NT GEMM, M=8192, N=1024, K=1024.
// ---------------------------------------------------------------------------
__global__ __launch_bounds__(256) void out_gemm(
    const float* __restrict__ Wo, const float* __restrict__ bo,
    const float* __restrict__ hidden, float* __restrict__ out)
{
    __shared__ float As[8][128];
    __shared__ float Ws[8][128];

    const int tx = threadIdx.x, ty = threadIdx.y;
    const int tid = ty * 16 + tx;
    const int m0 = blockIdx.y * 128;
    const int n0 = blockIdx.x * 128;

    float acc[8][8];
#pragma unroll
    for (int i = 0; i < 8; i++)
#pragma unroll
        for (int j = 0; j < 8; j++) acc[i][j] = 0.f;

    const int lrow = tid >> 1;
    const int lkq  = (tid & 1) * 4;

    for (int k0 = 0; k0 < HID; k0 += 8) {
        float4 va = *(const float4*)(g_ctx + (long long)(m0 + lrow) * HID + k0 + lkq);
        As[lkq + 0][lrow] = va.x; As[lkq + 1][lrow] = va.y;
        As[lkq + 2][lrow] = va.z; As[lkq + 3][lrow] = va.w;
        float4 vw = *(const float4*)(Wo + (long long)(n0 + lrow) * HID + k0 + lkq);
        Ws[lkq + 0][lrow] = vw.x; Ws[lkq + 1][lrow] = vw.y;
        Ws[lkq + 2][lrow] = vw.z; Ws[lkq + 3][lrow] = vw.w;
        __syncthreads();

#pragma unroll
        for (int kk = 0; kk < 8; kk++) {
            float a[8], w[8];
            *(float4*)(a)     = *(const float4*)&As[kk][ty * 8];
            *(float4*)(a + 4) = *(const float4*)&As[kk][ty * 8 + 4];
            *(float4*)(w)     = *(const float4*)&Ws[kk][tx * 8];
            *(float4*)(w + 4) = *(const float4*)&Ws[kk][tx * 8 + 4];
#pragma unroll
            for (int i = 0; i < 8; i++)
#pragma unroll
                for (int j = 0; j < 8; j++)
                    acc[i][j] = fmaf(a[i], w[j], acc[i][j]);
        }
        __syncthreads();
    }

#pragma unroll
    for (int i = 0; i < 8; i++) {
        const long long m = m0 + ty * 8 + i;
#pragma unroll
        for (int j = 0; j < 8; j++) {
            const int n = n0 + tx * 8 + j;
            out[m * HID + n] = acc[i][j] + bo[n] + hidden[m * HID + n];
        }
    }
}

// ---------------------------------------------------------------------------
extern "C" void kernel_launch(void* const* d_in, const int* in_sizes, int n_in,
                              void* d_out, int out_size)
{
    const float* X  = (const float*)d_in[0];
    const float* Wq = (const float*)d_in[1];
    const float* bq = (const float*)d_in[2];
    const float* Wk = (const float*)d_in[3];
    const float* bk = (const float*)d_in[4];
    const float* Wv = (const float*)d_in[5];
    const float* bv = (const float*)d_in[6];
    const float* Wo = (const float*)d_in[7];
    const float* bo = (const float*)d_in[8];

    float* out   = (float*)d_out;
    float* probs = out + OUT_ELEMS;

    dim3 thr(16, 16);

    // 1) QKV projections (pproc == plain linear in forward)
    qkv_gemm<<<dim3(HID / 128, MROWS / 128, 3), thr>>>(X, Wq, bq, Wk, bk, Wv, bv);

    // 2) scores = Q K^T (no scaling), written into probs region
    scores_gemm<<<dim3(SEQ / 128, SEQ / 128, BATCH * NHEAD), thr>>>(probs);

    // 3) softmax rows in place
    softmax_rows<<<BATCH * NHEAD * SEQ, 256>>>(probs);

    // 4) ctx = probs @ V
    ctx_gemm<<<dim3(1, SEQ / 128, BATCH * NHEAD), thr>>>(probs);

    // 5) out = ctx @ Wo^T + bo + hidden
    out_gemm<<<dim3(HID / 128, MROWS / 128), thr>>>(Wo, bo, X, out);
}

// round 3
// speedup vs baseline: 1.7184x; 1.7184x over previous
#include <cuda_runtime.h>
#include <cuda_bf16.h>
#include <cstdint>

// ---------------------------------------------------------------------------
constexpr int BATCH = 4;
constexpr int SEQ   = 2048;
constexpr int HID   = 1024;
constexpr int NHEAD = 16;
constexpr int HDIM  = 64;
constexpr int MROWS = BATCH * SEQ;                       // 8192
constexpr long long OUT_ELEMS = (long long)MROWS * HID;  // 8,388,608

constexpr int LDT = 40;                       // bf16 elems per smem tile row
constexpr int TILEA_B = 128 * LDT * 2;        // 10240 bytes (128-row tile)
constexpr int TILEV_B = 64 * LDT * 2;         // 5120 bytes  (64-row tile)
constexpr int BUF_QKV = 4 * TILEA_B;          // Ah,Al,Bh,Bl
constexpr int BUF_CTX = 2 * TILEA_B + 2 * TILEV_B;
constexpr int SMEM_QKV = 2 * BUF_QKV;                     // 81920
constexpr int SMEM_SC  = 2 * BUF_QKV + 128 * 4 * 8;       // + stats
constexpr int SMEM_CTX = 2 * BUF_CTX;                     // 61440

// Scratch
__device__ float g_q[BATCH * NHEAD * SEQ * HDIM];
__device__ float g_k[BATCH * NHEAD * SEQ * HDIM];
__device__ float g_v[BATCH * NHEAD * SEQ * HDIM];
__device__ float g_ctx[BATCH * SEQ * HID];
__device__ float g_pmax[64 * 16 * SEQ];
__device__ float g_psum[64 * 16 * SEQ];
__device__ float g_rmax[64 * SEQ];
__device__ float g_rinv[64 * SEQ];

// ---------------------------------------------------------------------------
__device__ __forceinline__ uint32_t smem_u32(const void* p) {
    uint32_t a;
    asm("{ .reg .u64 t; cvta.to.shared.u64 t, %1; cvt.u32.u64 %0, t; }"
        : "=r"(a) : "l"(p));
    return a;
}

__device__ __forceinline__ void ldsm4(uint32_t* r, uint32_t a) {
    asm volatile("ldmatrix.sync.aligned.m8n8.x4.shared.b16 {%0,%1,%2,%3}, [%4];"
                 : "=r"(r[0]), "=r"(r[1]), "=r"(r[2]), "=r"(r[3]) : "r"(a));
}

#define MMA_BF16(d, a, b0, b1)                                              \
    asm volatile(                                                           \
        "mma.sync.aligned.m16n8k16.row.col.f32.bf16.bf16.f32 "              \
        "{%0,%1,%2,%3}, {%4,%5,%6,%7}, {%8,%9}, {%0,%1,%2,%3};"             \
        : "+f"((d)[0]), "+f"((d)[1]), "+f"((d)[2]), "+f"((d)[3])            \
        : "r"((a)[0]), "r"((a)[1]), "r"((a)[2]), "r"((a)[3]),               \
          "r"(b0), "r"(b1))

__device__ __forceinline__ void pack_hl(float x, float y, uint32_t& h, uint32_t& l) {
    __nv_bfloat16 hx = __float2bfloat16(x);
    __nv_bfloat16 hy = __float2bfloat16(y);
    __nv_bfloat16 lx = __float2bfloat16(x - __bfloat162float(hx));
    __nv_bfloat16 ly = __float2bfloat16(y - __bfloat162float(hy));
    h = ((uint32_t)__bfloat16_as_ushort(hy) << 16) | __bfloat16_as_ushort(hx);
    l = ((uint32_t)__bfloat16_as_ushort(ly) << 16) | __bfloat16_as_ushort(lx);
}

// ---------------------------------------------------------------------------
// Generic split-bf16 warp MMA over one 32-wide K chunk (two k16 steps).
// Tiles are [rows][LDT] bf16 in SMEM.  acc layout: [MF][NF][4].
// ---------------------------------------------------------------------------
template <int MF, int NF>
__device__ __forceinline__ void mma_chunk(float (&acc)[MF][NF][4],
                                          uint32_t aHi, uint32_t aLo,
                                          uint32_t bHi, uint32_t bLo,
                                          int mbase, int nbase, int lane)
{
    const int r16 = lane & 15;
    const int koL = (lane >> 4) * 16;   // byte offset of 8-bf16 column half
#pragma unroll
    for (int ks = 0; ks < 2; ks++) {
        const int kb = ks * 32 + koL;
        uint32_t FA[4 * MF], FB[2 * NF], FC[2 * NF];
#pragma unroll
        for (int mf = 0; mf < MF; mf++)
            ldsm4(&FA[4 * mf], aHi + (mbase + mf * 16 + r16) * (LDT * 2) + kb);
#pragma unroll
        for (int nb = 0; nb < NF / 2; nb++)
            ldsm4(&FB[4 * nb], bHi + (nbase + nb * 16 + r16) * (LDT * 2) + kb);
#pragma unroll
        for (int mf = 0; mf < MF; mf++)
#pragma unroll
            for (int nf = 0; nf < NF; nf++)
                MMA_BF16(acc[mf][nf], &FA[4 * mf],
                         FB[4 * (nf >> 1) + (nf & 1)], FB[4 * (nf >> 1) + 2 + (nf & 1)]);
#pragma unroll
        for (int nb = 0; nb < NF / 2; nb++)
            ldsm4(&FC[4 * nb], bLo + (nbase + nb * 16 + r16) * (LDT * 2) + kb);
#pragma unroll
        for (int mf = 0; mf < MF; mf++)
#pragma unroll
            for (int nf = 0; nf < NF; nf++)
                MMA_BF16(acc[mf][nf], &FA[4 * mf],
                         FC[4 * (nf >> 1) + (nf & 1)], FC[4 * (nf >> 1) + 2 + (nf & 1)]);
#pragma unroll
        for (int mf = 0; mf < MF; mf++)
            ldsm4(&FA[4 * mf], aLo + (mbase + mf * 16 + r16) * (LDT * 2) + kb);
#pragma unroll
        for (int mf = 0; mf < MF; mf++)
#pragma unroll
            for (int nf = 0; nf < NF; nf++)
                MMA_BF16(acc[mf][nf], &FA[4 * mf],
                         FB[4 * (nf >> 1) + (nf & 1)], FB[4 * (nf >> 1) + 2 + (nf & 1)]);
    }
}

// ---------------------------------------------------------------------------
// 128x32 fp32 tile loaders: thread = (row = tid>>1, half = tid&1)
// ---------------------------------------------------------------------------
__device__ __forceinline__ void ldg_128x32(const float* __restrict__ src,
                                           long long ld, int tid, float4 v[4]) {
    const int row = tid >> 1, half = tid & 1;
    const float* p = src + (long long)row * ld + half * 16;
    v[0] = ((const float4*)p)[0];
    v[1] = ((const float4*)p)[1];
    v[2] = ((const float4*)p)[2];
    v[3] = ((const float4*)p)[3];
}

__device__ __forceinline__ void sts_128x32(const float4 v[4],
                                           char* hi, char* lo, int tid) {
    const int row = tid >> 1, half = tid & 1;
    uint32_t h[8], l[8];
    pack_hl(v[0].x, v[0].y, h[0], l[0]); pack_hl(v[0].z, v[0].w, h[1], l[1]);
    pack_hl(v[1].x, v[1].y, h[2], l[2]); pack_hl(v[1].z, v[1].w, h[3], l[3]);
    pack_hl(v[2].x, v[2].y, h[4], l[4]); pack_hl(v[2].z, v[2].w, h[5], l[5]);
    pack_hl(v[3].x, v[3].y, h[6], l[6]); pack_hl(v[3].z, v[3].w, h[7], l[7]);
    char* ph = hi + row * (LDT * 2) + half * 32;
    char* pl = lo + row * (LDT * 2) + half * 32;
    ((uint4*)ph)[0] = make_uint4(h[0], h[1], h[2], h[3]);
    ((uint4*)ph)[1] = make_uint4(h[4], h[5], h[6], h[7]);
    ((uint4*)pl)[0] = make_uint4(l[0], l[1], l[2], l[3]);
    ((uint4*)pl)[1] = make_uint4(l[4], l[5], l[6], l[7]);
}

// ctx A variant: apply softmax transform, write normalized probs back.
__device__ __forceinline__ void sts_128x32_sm(float4 v[4], char* hi, char* lo,
                                              int tid, float rm, float ri,
                                              float* __restrict__ wb) {
    const int half = tid & 1;
#pragma unroll
    for (int q = 0; q < 4; q++) {
        v[q].x = __expf(v[q].x - rm) * ri;
        v[q].y = __expf(v[q].y - rm) * ri;
        v[q].z = __expf(v[q].z - rm) * ri;
        v[q].w = __expf(v[q].w - rm) * ri;
        ((float4*)(wb + half * 16))[q] = v[q];
    }
    sts_128x32(v, hi, lo, tid);
}

// V^T loader: 64(n) x 32(k) tile from V chunk [k][n] (k-stride HDIM)
__device__ __forceinline__ void ldg_vT(const float* __restrict__ Vc, int tid, float x[8]) {
    const int n = tid >> 2, kq = (tid & 3) * 8;
#pragma unroll
    for (int j = 0; j < 8; j++) x[j] = Vc[(long long)(kq + j) * HDIM + n];
}
__device__ __forceinline__ void sts_vT(const float x[8], char* hi, char* lo, int tid) {
    const int n = tid >> 2, kq = (tid & 3) * 8;
    uint32_t h[4], l[4];
    pack_hl(x[0], x[1], h[0], l[0]); pack_hl(x[2], x[3], h[1], l[1]);
    pack_hl(x[4], x[5], h[2], l[2]); pack_hl(x[6], x[7], h[3], l[3]);
    *(uint4*)(hi + n * (LDT * 2) + kq * 2) = make_uint4(h[0], h[1], h[2], h[3]);
    *(uint4*)(lo + n * (LDT * 2) + kq * 2) = make_uint4(l[0], l[1], l[2], l[3]);
}

// ---------------------------------------------------------------------------
// QKV projection: C = X @ W^T + b -> [b,h,s,d].  grid(8, 64, 3), 256 thr.
// ---------------------------------------------------------------------------
__global__ void __launch_bounds__(256, 1) mm_qkv(
    const float* __restrict__ X,
    const float* __restrict__ Wq, const float* __restrict__ bq,
    const float* __restrict__ Wk, const float* __restrict__ bk,
    const float* __restrict__ Wv, const float* __restrict__ bv)
{
    extern __shared__ char sm[];
    const float* W; const float* bias; float* dst;
    if (blockIdx.z == 0)      { W = Wq; bias = bq; dst = g_q; }
    else if (blockIdx.z == 1) { W = Wk; bias = bk; dst = g_k; }
    else                      { W = Wv; bias = bv; dst = g_v; }

    const int tid = threadIdx.x, lane = tid & 31, wid = tid >> 5;
    const int mw = wid >> 2, nw = wid & 3;          // 2 x 4 warp grid
    const int m0 = blockIdx.y * 128, n0 = blockIdx.x * 128;
    const float* A = X + (long long)m0 * HID;
    const float* B = W + (long long)n0 * HID;

    float acc[4][4][4];
#pragma unroll
    for (int i = 0; i < 4; i++)
#pragma unroll
        for (int j = 0; j < 4; j++)
#pragma unroll
            for (int q = 0; q < 4; q++) acc[i][j][q] = 0.f;

    float4 va[4], vb[4];
    ldg_128x32(A, HID, tid, va);
    ldg_128x32(B, HID, tid, vb);
    sts_128x32(va, sm, sm + TILEA_B, tid);
    sts_128x32(vb, sm + 2 * TILEA_B, sm + 3 * TILEA_B, tid);
    __syncthreads();

    for (int c = 0; c < 32; c++) {
        char* buf = sm + (c & 1) * BUF_QKV;
        if (c + 1 < 32) {
            ldg_128x32(A + (c + 1) * 32, HID, tid, va);
            ldg_128x32(B + (c + 1) * 32, HID, tid, vb);
        }
        mma_chunk<4, 4>(acc, smem_u32(buf), smem_u32(buf + TILEA_B),
                        smem_u32(buf + 2 * TILEA_B), smem_u32(buf + 3 * TILEA_B),
                        mw * 64, nw * 32, lane);
        if (c + 1 < 32) {
            char* nb = sm + ((c + 1) & 1) * BUF_QKV;
            sts_128x32(va, nb, nb + TILEA_B, tid);
            sts_128x32(vb, nb + 2 * TILEA_B, nb + 3 * TILEA_B, tid);
        }
        __syncthreads();
    }

    const int g = lane >> 2, tig = lane & 3;
#pragma unroll
    for (int mf = 0; mf < 4; mf++) {
#pragma unroll
        for (int half = 0; half < 2; half++) {
            const int m = m0 + mw * 64 + mf * 16 + g + half * 8;
            const int b = m >> 11, s = m & 2047;
#pragma unroll
            for (int nf = 0; nf < 4; nf++) {
                const int n = n0 + nw * 32 + nf * 8 + tig * 2;
                const int h = n >> 6, d = n & 63;
                float2 st;
                st.x = acc[mf][nf][half * 2 + 0] + bias[n + 0];
                st.y = acc[mf][nf][half * 2 + 1] + bias[n + 1];
                *(float2*)(dst + (((long long)(b * NHEAD + h)) * SEQ + s) * HDIM + d) = st;
            }
        }
    }
}

// ---------------------------------------------------------------------------
// Scores: raw S = Q K^T written to probs region + per-(row, 128-block)
// max/sumexp partials.  grid(16, 16, 64), 256 thr.
// ---------------------------------------------------------------------------
__global__ void __launch_bounds__(256, 1) mm_scores(float* __restrict__ probs)
{
    extern __shared__ char sm[];
    const int tid = threadIdx.x, lane = tid & 31, wid = tid >> 5;
    const int mw = wid >> 2, nw = wid & 3;
    const int bh = blockIdx.z;
    const int m0 = blockIdx.y * 128, n0 = blockIdx.x * 128;
    const float* A = g_q + ((long long)bh * SEQ + m0) * HDIM;
    const float* B = g_k + ((long long)bh * SEQ + n0) * HDIM;
    float* C = probs + (long long)bh * SEQ * SEQ;

    float acc[4][4][4];
#pragma unroll
    for (int i = 0; i < 4; i++)
#pragma unroll
        for (int j = 0; j < 4; j++)
#pragma unroll
            for (int q = 0; q < 4; q++) acc[i][j][q] = 0.f;

    float4 va[4], vb[4];
    ldg_128x32(A, HDIM, tid, va);
    ldg_128x32(B, HDIM, tid, vb);
    sts_128x32(va, sm, sm + TILEA_B, tid);
    sts_128x32(vb, sm + 2 * TILEA_B, sm + 3 * TILEA_B, tid);
    __syncthreads();

    for (int c = 0; c < 2; c++) {
        char* buf = sm + (c & 1) * BUF_QKV;
        if (c + 1 < 2) {
            ldg_128x32(A + 32, HDIM, tid, va);
            ldg_128x32(B + 32, HDIM, tid, vb);
        }
        mma_chunk<4, 4>(acc, smem_u32(buf), smem_u32(buf + TILEA_B),
                        smem_u32(buf + 2 * TILEA_B), smem_u32(buf + 3 * TILEA_B),
                        mw * 64, nw * 32, lane);
        if (c + 1 < 2) {
            char* nb = sm + BUF_QKV;
            sts_128x32(va, nb, nb + TILEA_B, tid);
            sts_128x32(vb, nb + 2 * TILEA_B, nb + 3 * TILEA_B, tid);
        }
        __syncthreads();
    }

    float2* stats = (float2*)(sm + 2 * BUF_QKV);   // [128][4]
    const int g = lane >> 2, tig = lane & 3;
#pragma unroll
    for (int mf = 0; mf < 4; mf++) {
#pragma unroll
        for (int half = 0; half < 2; half++) {
            const int rloc = mw * 64 + mf * 16 + g + half * 8;
            const long long m = m0 + rloc;
            float mx = -1e30f;
#pragma unroll
            for (int nf = 0; nf < 4; nf++) {
                mx = fmaxf(mx, fmaxf(acc[mf][nf][half * 2], acc[mf][nf][half * 2 + 1]));
            }
            float sx = 0.f;
#pragma unroll
            for (int nf = 0; nf < 4; nf++) {
                sx += __expf(acc[mf][nf][half * 2] - mx);
                sx += __expf(acc[mf][nf][half * 2 + 1] - mx);
                float2 st;
                st.x = acc[mf][nf][half * 2 + 0];
                st.y = acc[mf][nf][half * 2 + 1];
                *(float2*)(C + m * SEQ + n0 + nw * 32 + nf * 8 + tig * 2) = st;
            }
#pragma unroll
            for (int o = 1; o <= 2; o <<= 1) {
                float om = __shfl_xor_sync(0xffffffffu, mx, o);
                float os = __shfl_xor_sync(0xffffffffu, sx, o);
                float nm = fmaxf(mx, om);
                sx = sx * __expf(mx - nm) + os * __expf(om - nm);
                mx = nm;
            }
            if (tig == 0) stats[rloc * 4 + nw] = make_float2(mx, sx);
        }
    }
    __syncthreads();
    if (tid < 128) {
        float M = -1e30f, S = 0.f;
#pragma unroll
        for (int w = 0; w < 4; w++) {
            float2 p = stats[tid * 4 + w];
            float nm = fmaxf(M, p.x);
            S = S * __expf(M - nm) + p.y * __expf(p.x - nm);
            M = nm;
        }
        const long long idx = ((long long)bh * 16 + blockIdx.x) * SEQ + m0 + tid;
        g_pmax[idx] = M;
        g_psum[idx] = S;
    }
}

// ---------------------------------------------------------------------------
// Combine per-block partials -> per-row max & 1/sum.  grid(512), 256 thr.
// ---------------------------------------------------------------------------
__global__ void __launch_bounds__(256) sm_reduce()
{
    const int idx = blockIdx.x * 256 + threadIdx.x;     // 0..131071
    const int bh = idx >> 11, s = idx & 2047;
    float M = -1e30f, S = 0.f;
#pragma unroll
    for (int t = 0; t < 16; t++) {
        const long long o = ((long long)bh * 16 + t) * SEQ + s;
        float m = g_pmax[o], sm_ = g_psum[o];
        float nm = fmaxf(M, m);
        S = S * __expf(M - nm) + sm_ * __expf(m - nm);
        M = nm;
    }
    g_rmax[idx] = M;
    g_rinv[idx] = 1.0f / S;
}

// ---------------------------------------------------------------------------
// Context: ctx = softmax(S) @ V; also writes normalized probs back.
// grid(16, 64), 256 thr.  Warp grid 4(m) x 2(n), warp tile 32x32.
// ---------------------------------------------------------------------------
__global__ void __launch_bounds__(256, 1) mm_ctx(float* __restrict__ probs)
{
    extern __shared__ char sm[];
    const int tid = threadIdx.x, lane = tid & 31, wid = tid >> 5;
    const int mw = wid >> 1, nw = wid & 1;
    const int bh = blockIdx.y;
    const int b = bh >> 4, h = bh & 15;
    const int m0 = blockIdx.x * 128;
    float* A = probs + ((long long)bh * SEQ + m0) * SEQ;
    const float* V = g_v + (long long)bh * SEQ * HDIM;

    const int lrow = tid >> 1;
    const float rm = g_rmax[bh * SEQ + m0 + lrow];
    const float ri = g_rinv[bh * SEQ + m0 + lrow];
    float* wbbase = A + (long long)lrow * SEQ;

    float acc[2][4][4];
#pragma unroll
    for (int i = 0; i < 2; i++)
#pragma unroll
        for (int j = 0; j < 4; j++)
#pragma unroll
            for (int q = 0; q < 4; q++) acc[i][j][q] = 0.f;

    float4 va[4]; float xv[8];
    ldg_128x32(A, SEQ, tid, va);
    ldg_vT(V, tid, xv);
    sts_128x32_sm(va, sm, sm + TILEA_B, tid, rm, ri, wbbase);
    sts_vT(xv, sm + 2 * TILEA_B, sm + 2 * TILEA_B + TILEV_B, tid);
    __syncthreads();

    for (int c = 0; c < 64; c++) {
        char* buf = sm + (c & 1) * BUF_CTX;
        if (c + 1 < 64) {
            ldg_128x32(A + (c + 1) * 32, SEQ, tid, va);
            ldg_vT(V + (long long)(c + 1) * 32 * HDIM, tid, xv);
        }
        mma_chunk<2, 4>(acc, smem_u32(buf), smem_u32(buf + TILEA_B),
                        smem_u32(buf + 2 * TILEA_B), smem_u32(buf + 2 * TILEA_B + TILEV_B),
                        mw * 32, nw * 32, lane);
        if (c + 1 < 64) {
            char* nb = sm + ((c + 1) & 1) * BUF_CTX;
            sts_128x32_sm(va, nb, nb + TILEA_B, tid, rm, ri, wbbase + (c + 1) * 32);
            sts_vT(xv, nb + 2 * TILEA_B, nb + 2 * TILEA_B + TILEV_B, tid);
        }
        __syncthreads();
    }

    const int g = lane >> 2, tig = lane & 3;
#pragma unroll
    for (int mf = 0; mf < 2; mf++) {
#pragma unroll
        for (int half = 0; half < 2; half++) {
            const int s = m0 + mw * 32 + mf * 16 + g + half * 8;
#pragma unroll
            for (int nf = 0; nf < 4; nf++) {
                const int d = nw * 32 + nf * 8 + tig * 2;
                float2 st;
                st.x = acc[mf][nf][half * 2 + 0];
                st.y = acc[mf][nf][half * 2 + 1];
                *(float2*)(g_ctx + ((long long)(b * SEQ + s)) * HID + h * HDIM + d) = st;
            }
        }
    }
}

// ---------------------------------------------------------------------------
// Output projection + residual.  grid(8, 64), 256 thr.
// ---------------------------------------------------------------------------
__global__ void __launch_bounds__(256, 1) mm_out(
    const float* __restrict__ Wo, const float* __restrict__ bo,
    const float* __restrict__ hidden, float* __restrict__ out)
{
    extern __shared__ char sm[];
    const int tid = threadIdx.x, lane = tid & 31, wid = tid >> 5;
    const int mw = wid >> 2, nw = wid & 3;
    const int m0 = blockIdx.y * 128, n0 = blockIdx.x * 128;
    const float* A = g_ctx + (long long)m0 * HID;
    const float* B = Wo + (long long)n0 * HID;

    float acc[4][4][4];
#pragma unroll
    for (int i = 0; i < 4; i++)
#pragma unroll
        for (int j = 0; j < 4; j++)
#pragma unroll
            for (int q = 0; q < 4; q++) acc[i][j][q] = 0.f;

    float4 va[4], vb[4];
    ldg_128x32(A, HID, tid, va);
    ldg_128x32(B, HID, tid, vb);
    sts_128x32(va, sm, sm + TILEA_B, tid);
    sts_128x32(vb, sm + 2 * TILEA_B, sm + 3 * TILEA_B, tid);
    __syncthreads();

    for (int c = 0; c < 32; c++) {
        char* buf = sm + (c & 1) * BUF_QKV;
        if (c + 1 < 32) {
            ldg_128x32(A + (c + 1) * 32, HID, tid, va);
            ldg_128x32(B + (c + 1) * 32, HID, tid, vb);
        }
        mma_chunk<4, 4>(acc, smem_u32(buf), smem_u32(buf + TILEA_B),
                        smem_u32(buf + 2 * TILEA_B), smem_u32(buf + 3 * TILEA_B),
                        mw * 64, nw * 32, lane);
        if (c + 1 < 32) {
            char* nb = sm + ((c + 1) & 1) * BUF_QKV;
            sts_128x32(va, nb, nb + TILEA_B, tid);
            sts_128x32(vb, nb + 2 * TILEA_B, nb + 3 * TILEA_B, tid);
        }
        __syncthreads();
    }

    const int g = lane >> 2, tig = lane & 3;
#pragma unroll
    for (int mf = 0; mf < 4; mf++) {
#pragma unroll
        for (int half = 0; half < 2; half++) {
            const long long m = m0 + mw * 64 + mf * 16 + g + half * 8;
#pragma unroll
            for (int nf = 0; nf < 4; nf++) {
                const int n = n0 + nw * 32 + nf * 8 + tig * 2;
                float2 hd = *(const float2*)(hidden + m * HID + n);
                float2 st;
                st.x = acc[mf][nf][half * 2 + 0] + bo[n + 0] + hd.x;
                st.y = acc[mf][nf][half * 2 + 1] + bo[n + 1] + hd.y;
                *(float2*)(out + m * HID + n) = st;
            }
        }
    }
}

// ---------------------------------------------------------------------------
extern "C" void kernel_launch(void* const* d_in, const int* in_sizes, int n_in,
                              void* d_out, int out_size)
{
    const float* X  = (const float*)d_in[0];
    const float* Wq = (const float*)d_in[1];
    const float* bq = (const float*)d_in[2];
    const float* Wk = (const float*)d_in[3];
    const float* bk = (const float*)d_in[4];
    const float* Wv = (const float*)d_in[5];
    const float* bv = (const float*)d_in[6];
    const float* Wo = (const float*)d_in[7];
    const float* bo = (const float*)d_in[8];

    float* out   = (float*)d_out;
    float* probs = out + OUT_ELEMS;

    cudaFuncSetAttribute(mm_qkv,    cudaFuncAttributeMaxDynamicSharedMemorySize, SMEM_QKV);
    cudaFuncSetAttribute(mm_scores, cudaFuncAttributeMaxDynamicSharedMemorySize, SMEM_SC);
    cudaFuncSetAttribute(mm_ctx,    cudaFuncAttributeMaxDynamicSharedMemorySize, SMEM_CTX);
    cudaFuncSetAttribute(mm_out,    cudaFuncAttributeMaxDynamicSharedMemorySize, SMEM_QKV);

    mm_qkv<<<dim3(HID / 128, MROWS / 128, 3), 256, SMEM_QKV>>>(X, Wq, bq, Wk, bk, Wv, bv);
    mm_scores<<<dim3(SEQ / 128, SEQ / 128, BATCH * NHEAD), 256, SMEM_SC>>>(probs);
    sm_reduce<<<BATCH * NHEAD * SEQ / 256, 256>>>();
    mm_ctx<<<dim3(SEQ / 128, BATCH * NHEAD), 256, SMEM_CTX>>>(probs);
    mm_out<<<dim3(HID / 128, MROWS / 128), 256, SMEM_QKV>>>(Wo, bo, X, out);
}

// round 4
// speedup vs baseline: 2.4667x; 1.4354x over previous
#include <cuda_runtime.h>
#include <cuda_bf16.h>
#include <cstdint>

// ---------------------------------------------------------------------------
constexpr int BATCH = 4;
constexpr int SEQ   = 2048;
constexpr int HID   = 1024;
constexpr int NHEAD = 16;
constexpr int HDIM  = 64;
constexpr int MROWS = BATCH * SEQ;                       // 8192
constexpr long long OUT_ELEMS = (long long)MROWS * HID;  // 8,388,608

// GEMM tiles: 32-col chunks, rows padded to 40 bf16 (80 B) -> conflict-free ldsm
constexpr int LDT = 40;
constexpr int TILE_B = 128 * LDT * 2;     // 10240
constexpr int GBUF   = 4 * TILE_B;        // Ah,Al,Bh,Bl per chunk buffer
constexpr int SMEM_G = 2 * GBUF;          // 81920

// Attention tiles: 64-col rows padded to 72 bf16 (144 B)
constexpr int LDA_B  = 144;
constexpr int ATILE  = 128 * LDA_B;       // 18432
// smem offsets
constexpr int OQH = 0, OQL = ATILE;
constexpr int OKH0 = 2 * ATILE, OKL0 = 3 * ATILE, OKH1 = 4 * ATILE, OKL1 = 5 * ATILE;
constexpr int OVH0 = 6 * ATILE, OVL0 = 7 * ATILE, OVH1 = 8 * ATILE, OVL1 = 9 * ATILE;
constexpr int SMEM_ATTN = 10 * ATILE;     // 184320

// ---------------------------------------------------------------------------
// Prepped bf16 hi/lo operands (device globals; no runtime allocation)
// ---------------------------------------------------------------------------
__device__ __nv_bfloat16 g_xh[MROWS * HID], g_xl[MROWS * HID];
__device__ __nv_bfloat16 g_wh[4 * HID * HID], g_wl[4 * HID * HID];
__device__ __nv_bfloat16 g_qh[64 * SEQ * HDIM], g_ql[64 * SEQ * HDIM];
__device__ __nv_bfloat16 g_kh[64 * SEQ * HDIM], g_kl[64 * SEQ * HDIM];
__device__ __nv_bfloat16 g_vh[64 * SEQ * HDIM], g_vl[64 * SEQ * HDIM];
__device__ __nv_bfloat16 g_ch[MROWS * HID], g_cl[MROWS * HID];

// ---------------------------------------------------------------------------
__device__ __forceinline__ uint32_t smem_u32(const void* p) {
    uint32_t a;
    asm("{ .reg .u64 t; cvta.to.shared.u64 t, %1; cvt.u32.u64 %0, t; }"
        : "=r"(a) : "l"(p));
    return a;
}

__device__ __forceinline__ void ldsm4(uint32_t* r, uint32_t a) {
    asm volatile("ldmatrix.sync.aligned.m8n8.x4.shared.b16 {%0,%1,%2,%3}, [%4];"
                 : "=r"(r[0]), "=r"(r[1]), "=r"(r[2]), "=r"(r[3]) : "r"(a));
}
__device__ __forceinline__ void ldsm4t(uint32_t* r, uint32_t a) {
    asm volatile("ldmatrix.sync.aligned.m8n8.x4.trans.shared.b16 {%0,%1,%2,%3}, [%4];"
                 : "=r"(r[0]), "=r"(r[1]), "=r"(r[2]), "=r"(r[3]) : "r"(a));
}

#define MMA_BF16(d, a, b0, b1)                                              \
    asm volatile(                                                           \
        "mma.sync.aligned.m16n8k16.row.col.f32.bf16.bf16.f32 "              \
        "{%0,%1,%2,%3}, {%4,%5,%6,%7}, {%8,%9}, {%0,%1,%2,%3};"             \
        : "+f"((d)[0]), "+f"((d)[1]), "+f"((d)[2]), "+f"((d)[3])            \
        : "r"((a)[0]), "r"((a)[1]), "r"((a)[2]), "r"((a)[3]),               \
          "r"(b0), "r"(b1))

__device__ __forceinline__ void cp16(uint32_t dst, const void* src) {
    asm volatile("cp.async.cg.shared.global [%0], [%1], 16;" :: "r"(dst), "l"(src));
}
#define CP_COMMIT asm volatile("cp.async.commit_group;" ::: "memory")
#define CP_WAIT1  asm volatile("cp.async.wait_group 1;" ::: "memory")
#define CP_WAIT0  asm volatile("cp.async.wait_group 0;" ::: "memory")

__device__ __forceinline__ void pack_hl(float x, float y, uint32_t& h, uint32_t& l) {
    __nv_bfloat16 hx = __float2bfloat16(x);
    __nv_bfloat16 hy = __float2bfloat16(y);
    __nv_bfloat16 lx = __float2bfloat16(x - __bfloat162float(hx));
    __nv_bfloat16 ly = __float2bfloat16(y - __bfloat162float(hy));
    h = ((uint32_t)__bfloat16_as_ushort(hy) << 16) | __bfloat16_as_ushort(hx);
    l = ((uint32_t)__bfloat16_as_ushort(ly) << 16) | __bfloat16_as_ushort(lx);
}

// ---------------------------------------------------------------------------
// prep: split X and the 4 weight matrices into bf16 hi/lo once.
// ---------------------------------------------------------------------------
__global__ void __launch_bounds__(256) prep(
    const float* __restrict__ X,  const float* __restrict__ Wq,
    const float* __restrict__ Wk, const float* __restrict__ Wv,
    const float* __restrict__ Wo)
{
    const long long NX = (long long)MROWS * HID;
    long long i = (long long)blockIdx.x * 256 + threadIdx.x;
    float v; __nv_bfloat16 *dh, *dl; long long o;
    if (i < NX) {
        v = X[i]; dh = g_xh; dl = g_xl; o = i;
    } else {
        long long j = i - NX;
        int w = (int)(j >> 20);
        long long r = j & 1048575;
        if (w == 0) v = Wq[r]; else if (w == 1) v = Wk[r];
        else if (w == 2) v = Wv[r]; else v = Wo[r];
        dh = g_wh; dl = g_wl; o = j;
    }
    __nv_bfloat16 hb = __float2bfloat16(v);
    dh[o] = hb;
    dl[o] = __float2bfloat16(v - __bfloat162float(hb));
}

// ---------------------------------------------------------------------------
// Split-bf16 warp MMA over one 32-wide K chunk (GEMM kernels, LDT=40).
// ---------------------------------------------------------------------------
template <int MF, int NF>
__device__ __forceinline__ void mma_chunk(float (&acc)[MF][NF][4],
                                          uint32_t aHi, uint32_t aLo,
                                          uint32_t bHi, uint32_t bLo,
                                          int mbase, int nbase, int lane)
{
    const int r16 = lane & 15;
    const int koL = (lane >> 4) * 16;
#pragma unroll
    for (int ks = 0; ks < 2; ks++) {
        const int kb = ks * 32 + koL;
        uint32_t FA[4 * MF], FB[2 * NF], FC[2 * NF];
#pragma unroll
        for (int mf = 0; mf < MF; mf++)
            ldsm4(&FA[4 * mf], aHi + (mbase + mf * 16 + r16) * (LDT * 2) + kb);
#pragma unroll
        for (int nb = 0; nb < NF / 2; nb++)
            ldsm4(&FB[4 * nb], bHi + (nbase + nb * 16 + r16) * (LDT * 2) + kb);
#pragma unroll
        for (int mf = 0; mf < MF; mf++)
#pragma unroll
            for (int nf = 0; nf < NF; nf++)
                MMA_BF16(acc[mf][nf], &FA[4 * mf],
                         FB[4 * (nf >> 1) + (nf & 1)], FB[4 * (nf >> 1) + 2 + (nf & 1)]);
#pragma unroll
        for (int nb = 0; nb < NF / 2; nb++)
            ldsm4(&FC[4 * nb], bLo + (nbase + nb * 16 + r16) * (LDT * 2) + kb);
#pragma unroll
        for (int mf = 0; mf < MF; mf++)
#pragma unroll
            for (int nf = 0; nf < NF; nf++)
                MMA_BF16(acc[mf][nf], &FA[4 * mf],
                         FC[4 * (nf >> 1) + (nf & 1)], FC[4 * (nf >> 1) + 2 + (nf & 1)]);
#pragma unroll
        for (int mf = 0; mf < MF; mf++)
            ldsm4(&FA[4 * mf], aLo + (mbase + mf * 16 + r16) * (LDT * 2) + kb);
#pragma unroll
        for (int mf = 0; mf < MF; mf++)
#pragma unroll
            for (int nf = 0; nf < NF; nf++)
                MMA_BF16(acc[mf][nf], &FA[4 * mf],
                         FB[4 * (nf >> 1) + (nf & 1)], FB[4 * (nf >> 1) + 2 + (nf & 1)]);
    }
}

// cp.async a 128x32 bf16 tile (ld = HID) into LDT=40 smem
__device__ __forceinline__ void cp_tile32(const __nv_bfloat16* __restrict__ src,
                                          uint32_t dst, int tid) {
#pragma unroll
    for (int i = 0; i < 2; i++) {
        int id = tid + i * 256;
        int r = id >> 2, c = id & 3;
        cp16(dst + r * (LDT * 2) + c * 16, src + (long long)r * HID + c * 8);
    }
}

// ---------------------------------------------------------------------------
// QKV projection from prepped bf16: C = X W^T + b -> q/k/v hi/lo [bh][s][d]
// grid(8, 64, 3), 256 thr
// ---------------------------------------------------------------------------
__global__ void __launch_bounds__(256, 2) mm_qkv(
    const float* __restrict__ bq, const float* __restrict__ bk,
    const float* __restrict__ bv)
{
    extern __shared__ char sm[];
    const int z = blockIdx.z;
    const float* bias = (z == 0) ? bq : (z == 1) ? bk : bv;
    __nv_bfloat16* dsth = (z == 0) ? g_qh : (z == 1) ? g_kh : g_vh;
    __nv_bfloat16* dstl = (z == 0) ? g_ql : (z == 1) ? g_kl : g_vl;

    const int tid = threadIdx.x, lane = tid & 31, wid = tid >> 5;
    const int mw = wid >> 2, nw = wid & 3;
    const int m0 = blockIdx.y * 128, n0 = blockIdx.x * 128;
    const __nv_bfloat16* Ah = g_xh + (long long)m0 * HID;
    const __nv_bfloat16* Al = g_xl + (long long)m0 * HID;
    const __nv_bfloat16* Bh = g_wh + (long long)z * HID * HID + (long long)n0 * HID;
    const __nv_bfloat16* Bl = g_wl + (long long)z * HID * HID + (long long)n0 * HID;
    const uint32_t s0 = smem_u32(sm);

    float acc[4][4][4];
#pragma unroll
    for (int i = 0; i < 4; i++)
#pragma unroll
        for (int j = 0; j < 4; j++)
#pragma unroll
            for (int q = 0; q < 4; q++) acc[i][j][q] = 0.f;

    cp_tile32(Ah, s0 + 0 * TILE_B, tid);
    cp_tile32(Al, s0 + 1 * TILE_B, tid);
    cp_tile32(Bh, s0 + 2 * TILE_B, tid);
    cp_tile32(Bl, s0 + 3 * TILE_B, tid);
    CP_COMMIT;

    for (int c = 0; c < 32; c++) {
        if (c + 1 < 32) {
            uint32_t nb = s0 + ((c + 1) & 1) * GBUF;
            cp_tile32(Ah + (c + 1) * 32, nb + 0 * TILE_B, tid);
            cp_tile32(Al + (c + 1) * 32, nb + 1 * TILE_B, tid);
            cp_tile32(Bh + (c + 1) * 32, nb + 2 * TILE_B, tid);
            cp_tile32(Bl + (c + 1) * 32, nb + 3 * TILE_B, tid);
            CP_COMMIT;
            CP_WAIT1;
        } else {
            CP_WAIT0;
        }
        __syncthreads();
        uint32_t buf = s0 + (c & 1) * GBUF;
        mma_chunk<4, 4>(acc, buf, buf + TILE_B, buf + 2 * TILE_B, buf + 3 * TILE_B,
                        mw * 64, nw * 32, lane);
        __syncthreads();
    }

    const int g = lane >> 2, tig = lane & 3;
#pragma unroll
    for (int mf = 0; mf < 4; mf++) {
#pragma unroll
        for (int half = 0; half < 2; half++) {
            const int m = m0 + mw * 64 + mf * 16 + g + half * 8;
            const int b = m >> 11, s = m & 2047;
#pragma unroll
            for (int nf = 0; nf < 4; nf++) {
                const int n = n0 + nw * 32 + nf * 8 + tig * 2;
                const int h = n >> 6, d = n & 63;
                float vx = acc[mf][nf][half * 2 + 0] + bias[n + 0];
                float vy = acc[mf][nf][half * 2 + 1] + bias[n + 1];
                uint32_t hw, lw;
                pack_hl(vx, vy, hw, lw);
                long long idx = ((long long)(b * NHEAD + h) * SEQ + s) * HDIM + d;
                *(uint32_t*)(dsth + idx) = hw;
                *(uint32_t*)(dstl + idx) = lw;
            }
        }
    }
}

// ---------------------------------------------------------------------------
// Fused two-pass attention: S = Q K^T, P = softmax(S) (written once),
// ctx = P V (bf16 hi/lo out).  grid(16, 64), 256 thr, 8 warps x 16 rows.
// ---------------------------------------------------------------------------
__device__ __forceinline__ void cp_tile64(const __nv_bfloat16* __restrict__ src,
                                          uint32_t dst, int tid) {
#pragma unroll
    for (int i = 0; i < 4; i++) {
        int id = tid + i * 256;
        int r = id >> 3, c = id & 7;
        cp16(dst + r * LDA_B + c * 16, src + (long long)r * HDIM + c * 8);
    }
}

// split S for one 16-col block (nfp): acc[0..3] cols +0..7, acc[4..7] cols +8..15
__device__ __forceinline__ void s_tile_nfp(float* acc,
                                           const uint32_t* FQh, const uint32_t* FQl,
                                           uint32_t kh, uint32_t kl, int nfp, int lane)
{
    const int r16 = lane & 15;
    const int koL = (lane >> 4) * 16;
    const uint32_t rowoff = (uint32_t)(nfp * 16 + r16) * LDA_B;
#pragma unroll
    for (int ks = 0; ks < 4; ks++) {
        uint32_t FBh[4], FBl[4];
        ldsm4(FBh, kh + rowoff + ks * 32 + koL);
        ldsm4(FBl, kl + rowoff + ks * 32 + koL);
        MMA_BF16(acc,     &FQh[4 * ks], FBh[0], FBh[2]);
        MMA_BF16(acc + 4, &FQh[4 * ks], FBh[1], FBh[3]);
        MMA_BF16(acc,     &FQh[4 * ks], FBl[0], FBl[2]);
        MMA_BF16(acc + 4, &FQh[4 * ks], FBl[1], FBl[3]);
        MMA_BF16(acc,     &FQl[4 * ks], FBh[0], FBh[2]);
        MMA_BF16(acc + 4, &FQl[4 * ks], FBh[1], FBh[3]);
    }
}

__global__ void __launch_bounds__(256, 1) attn(float* __restrict__ probs)
{
    extern __shared__ char sm[];
    const int tid = threadIdx.x, lane = tid & 31, w = tid >> 5;
    const int g = lane >> 2, tig = lane & 3;
    const int bh = blockIdx.y;
    const int m0 = blockIdx.x * 128;
    const uint32_t s0 = smem_u32(sm);

    const __nv_bfloat16* Qh = g_qh + ((long long)bh * SEQ + m0) * HDIM;
    const __nv_bfloat16* Ql = g_ql + ((long long)bh * SEQ + m0) * HDIM;
    const __nv_bfloat16* Kh = g_kh + (long long)bh * SEQ * HDIM;
    const __nv_bfloat16* Kl = g_kl + (long long)bh * SEQ * HDIM;
    const __nv_bfloat16* Vh = g_vh + (long long)bh * SEQ * HDIM;
    const __nv_bfloat16* Vl = g_vl + (long long)bh * SEQ * HDIM;
    float* C = probs + (long long)bh * SEQ * SEQ;

    // Q tile + first K tile
    cp_tile64(Qh, s0 + OQH, tid);
    cp_tile64(Ql, s0 + OQL, tid);
    cp_tile64(Kh, s0 + OKH0, tid);
    cp_tile64(Kl, s0 + OKL0, tid);
    CP_COMMIT;
    CP_WAIT0;
    __syncthreads();

    // Q fragments (constant for whole kernel)
    uint32_t FQh[16], FQl[16];
    {
        const uint32_t arow = (uint32_t)(w * 16 + (lane & 15)) * LDA_B;
        const uint32_t koL = (lane >> 4) * 16;
#pragma unroll
        for (int ks = 0; ks < 4; ks++) {
            ldsm4(&FQh[4 * ks], s0 + OQH + arow + ks * 32 + koL);
            ldsm4(&FQl[4 * ks], s0 + OQL + arow + ks * 32 + koL);
        }
    }

    // ---------------- pass A: row sums of exp(S) ----------------
    float sum0 = 0.f, sum1 = 0.f;
    for (int j = 0; j < 16; j++) {
        if (j + 1 < 16) {
            uint32_t kb = s0 + (((j + 1) & 1) ? OKH1 : OKH0);
            cp_tile64(Kh + (long long)(j + 1) * 128 * HDIM, kb, tid);
            cp_tile64(Kl + (long long)(j + 1) * 128 * HDIM, kb + ATILE, tid);
            CP_COMMIT;
            CP_WAIT1;
        } else {
            CP_WAIT0;
        }
        __syncthreads();
        const uint32_t kh = s0 + ((j & 1) ? OKH1 : OKH0);
        const uint32_t kl = kh + ATILE;
#pragma unroll
        for (int nfp = 0; nfp < 8; nfp++) {
            float acc[8] = {0.f, 0.f, 0.f, 0.f, 0.f, 0.f, 0.f, 0.f};
            s_tile_nfp(acc, FQh, FQl, kh, kl, nfp, lane);
            sum0 += __expf(acc[0]) + __expf(acc[1]) + __expf(acc[4]) + __expf(acc[5]);
            sum1 += __expf(acc[2]) + __expf(acc[3]) + __expf(acc[6]) + __expf(acc[7]);
        }
        __syncthreads();
    }
#pragma unroll
    for (int o = 1; o <= 2; o <<= 1) {
        sum0 += __shfl_xor_sync(0xffffffffu, sum0, o);
        sum1 += __shfl_xor_sync(0xffffffffu, sum1, o);
    }
    const float ri0 = 1.0f / sum0;
    const float ri1 = 1.0f / sum1;

    // ---------------- pass B: write P, accumulate ctx = P V ----------------
    float ctx[8][4];
#pragma unroll
    for (int i = 0; i < 8; i++)
#pragma unroll
        for (int q = 0; q < 4; q++) ctx[i][q] = 0.f;

    cp_tile64(Kh, s0 + OKH0, tid);
    cp_tile64(Kl, s0 + OKL0, tid);
    cp_tile64(Vh, s0 + OVH0, tid);
    cp_tile64(Vl, s0 + OVL0, tid);
    CP_COMMIT;

    const long long rowg = m0 + w * 16 + g;

    for (int j = 0; j < 16; j++) {
        if (j + 1 < 16) {
            uint32_t kb = s0 + (((j + 1) & 1) ? OKH1 : OKH0);
            uint32_t vb = s0 + (((j + 1) & 1) ? OVH1 : OVH0);
            cp_tile64(Kh + (long long)(j + 1) * 128 * HDIM, kb, tid);
            cp_tile64(Kl + (long long)(j + 1) * 128 * HDIM, kb + ATILE, tid);
            cp_tile64(Vh + (long long)(j + 1) * 128 * HDIM, vb, tid);
            cp_tile64(Vl + (long long)(j + 1) * 128 * HDIM, vb + ATILE, tid);
            CP_COMMIT;
            CP_WAIT1;
        } else {
            CP_WAIT0;
        }
        __syncthreads();
        const uint32_t kh = s0 + ((j & 1) ? OKH1 : OKH0);
        const uint32_t kl = kh + ATILE;
        const uint32_t vh = s0 + ((j & 1) ? OVH1 : OVH0);
        const uint32_t vl = vh + ATILE;
        // V ldsm.trans base address for this thread
        const uint32_t vlanerow = (uint32_t)((lane & 7) + ((lane >> 4) & 1) * 8) * LDA_B
                                  + ((lane >> 3) & 1) * 16;

#pragma unroll
        for (int nfp = 0; nfp < 8; nfp++) {
            float acc[8] = {0.f, 0.f, 0.f, 0.f, 0.f, 0.f, 0.f, 0.f};
            s_tile_nfp(acc, FQh, FQl, kh, kl, nfp, lane);
            // normalized probs
            float pE0 = __expf(acc[0]) * ri0, pE1 = __expf(acc[1]) * ri0;
            float pE2 = __expf(acc[2]) * ri1, pE3 = __expf(acc[3]) * ri1;
            float pO0 = __expf(acc[4]) * ri0, pO1 = __expf(acc[5]) * ri0;
            float pO2 = __expf(acc[6]) * ri1, pO3 = __expf(acc[7]) * ri1;
            // write P (streaming)
            float* Cr = C + rowg * SEQ + j * 128 + nfp * 16 + tig * 2;
            __stcs((float2*)Cr,                 make_float2(pE0, pE1));
            __stcs((float2*)(Cr + 8),           make_float2(pO0, pO1));
            __stcs((float2*)(Cr + 8 * SEQ),     make_float2(pE2, pE3));
            __stcs((float2*)(Cr + 8 * SEQ + 8), make_float2(pO2, pO3));
            // convert to A-fragments (k16 slice = this 16-col block)
            uint32_t PAh[4], PAl[4];
            pack_hl(pE0, pE1, PAh[0], PAl[0]);
            pack_hl(pE2, pE3, PAh[1], PAl[1]);
            pack_hl(pO0, pO1, PAh[2], PAl[2]);
            pack_hl(pO2, pO3, PAh[3], PAl[3]);
            // V fragments for this k-slice (s rows nfp*16..+15), d = 0..63
            uint32_t FVh[16], FVl[16];
            const uint32_t vbase = (uint32_t)(nfp * 16) * LDA_B + vlanerow;
#pragma unroll
            for (int gd = 0; gd < 4; gd++) {
                ldsm4t(&FVh[4 * gd], vh + vbase + gd * 32);
                ldsm4t(&FVl[4 * gd], vl + vbase + gd * 32);
            }
#pragma unroll
            for (int dnf = 0; dnf < 8; dnf++) {
                const int j0 = 4 * (dnf >> 1) + (dnf & 1);
                MMA_BF16(ctx[dnf], PAh, FVh[j0], FVh[j0 + 2]);
                MMA_BF16(ctx[dnf], PAh, FVl[j0], FVl[j0 + 2]);
                MMA_BF16(ctx[dnf], PAl, FVh[j0], FVh[j0 + 2]);
            }
        }
        __syncthreads();
    }

    // ctx epilogue -> bf16 hi/lo [b][s][h*64+d]
    const int b = bh >> 4, h = bh & 15;
    const int s = m0 + w * 16 + g;
    const long long base = ((long long)(b * SEQ + s)) * HID + h * HDIM;
#pragma unroll
    for (int dnf = 0; dnf < 8; dnf++) {
        const int d = dnf * 8 + tig * 2;
        uint32_t hw, lw;
        pack_hl(ctx[dnf][0], ctx[dnf][1], hw, lw);
        *(uint32_t*)(g_ch + base + d) = hw;
        *(uint32_t*)(g_cl + base + d) = lw;
        pack_hl(ctx[dnf][2], ctx[dnf][3], hw, lw);
        *(uint32_t*)(g_ch + base + 8LL * HID + d) = hw;
        *(uint32_t*)(g_cl + base + 8LL * HID + d) = lw;
    }
}

// ---------------------------------------------------------------------------
// Output projection + residual: out = ctx Wo^T + bo + hidden.  grid(8, 64).
// ---------------------------------------------------------------------------
__global__ void __launch_bounds__(256, 2) mm_out(
    const float* __restrict__ bo, const float* __restrict__ hidden,
    float* __restrict__ out)
{
    extern __shared__ char sm[];
    const int tid = threadIdx.x, lane = tid & 31, wid = tid >> 5;
    const int mw = wid >> 2, nw = wid & 3;
    const int m0 = blockIdx.y * 128, n0 = blockIdx.x * 128;
    const __nv_bfloat16* Ah = g_ch + (long long)m0 * HID;
    const __nv_bfloat16* Al = g_cl + (long long)m0 * HID;
    const __nv_bfloat16* Bh = g_wh + 3LL * HID * HID + (long long)n0 * HID;
    const __nv_bfloat16* Bl = g_wl + 3LL * HID * HID + (long long)n0 * HID;
    const uint32_t s0 = smem_u32(sm);

    float acc[4][4][4];
#pragma unroll
    for (int i = 0; i < 4; i++)
#pragma unroll
        for (int j = 0; j < 4; j++)
#pragma unroll
            for (int q = 0; q < 4; q++) acc[i][j][q] = 0.f;

    cp_tile32(Ah, s0 + 0 * TILE_B, tid);
    cp_tile32(Al, s0 + 1 * TILE_B, tid);
    cp_tile32(Bh, s0 + 2 * TILE_B, tid);
    cp_tile32(Bl, s0 + 3 * TILE_B, tid);
    CP_COMMIT;

    for (int c = 0; c < 32; c++) {
        if (c + 1 < 32) {
            uint32_t nb = s0 + ((c + 1) & 1) * GBUF;
            cp_tile32(Ah + (c + 1) * 32, nb + 0 * TILE_B, tid);
            cp_tile32(Al + (c + 1) * 32, nb + 1 * TILE_B, tid);
            cp_tile32(Bh + (c + 1) * 32, nb + 2 * TILE_B, tid);
            cp_tile32(Bl + (c + 1) * 32, nb + 3 * TILE_B, tid);
            CP_COMMIT;
            CP_WAIT1;
        } else {
            CP_WAIT0;
        }
        __syncthreads();
        uint32_t buf = s0 + (c & 1) * GBUF;
        mma_chunk<4, 4>(acc, buf, buf + TILE_B, buf + 2 * TILE_B, buf + 3 * TILE_B,
                        mw * 64, nw * 32, lane);
        __syncthreads();
    }

    const int g = lane >> 2, tig = lane & 3;
#pragma unroll
    for (int mf = 0; mf < 4; mf++) {
#pragma unroll
        for (int half = 0; half < 2; half++) {
            const long long m = m0 + mw * 64 + mf * 16 + g + half * 8;
#pragma unroll
            for (int nf = 0; nf < 4; nf++) {
                const int n = n0 + nw * 32 + nf * 8 + tig * 2;
                float2 hd = *(const float2*)(hidden + m * HID + n);
                float2 st;
                st.x = acc[mf][nf][half * 2 + 0] + bo[n + 0] + hd.x;
                st.y = acc[mf][nf][half * 2 + 1] + bo[n + 1] + hd.y;
                *(float2*)(out + m * HID + n) = st;
            }
        }
    }
}

// ---------------------------------------------------------------------------
extern "C" void kernel_launch(void* const* d_in, const int* in_sizes, int n_in,
                              void* d_out, int out_size)
{
    const float* X  = (const float*)d_in[0];
    const float* Wq = (const float*)d_in[1];
    const float* bq = (const float*)d_in[2];
    const float* Wk = (const float*)d_in[3];
    const float* bk = (const float*)d_in[4];
    const float* Wv = (const float*)d_in[5];
    const float* bv = (const float*)d_in[6];
    const float* Wo = (const float*)d_in[7];
    const float* bo = (const float*)d_in[8];

    float* out   = (float*)d_out;
    float* probs = out + OUT_ELEMS;

    cudaFuncSetAttribute(mm_qkv, cudaFuncAttributeMaxDynamicSharedMemorySize, SMEM_G);
    cudaFuncSetAttribute(mm_out, cudaFuncAttributeMaxDynamicSharedMemorySize, SMEM_G);
    cudaFuncSetAttribute(attn,   cudaFuncAttributeMaxDynamicSharedMemorySize, SMEM_ATTN);

    const long long NPREP = (long long)MROWS * HID + 4LL * HID * HID;
    prep<<<(unsigned)((NPREP + 255) / 256), 256>>>(X, Wq, Wk, Wv, Wo);
    mm_qkv<<<dim3(HID / 128, MROWS / 128, 3), 256, SMEM_G>>>(bq, bk, bv);
    attn<<<dim3(SEQ / 128, BATCH * NHEAD), 256, SMEM_ATTN>>>(probs);
    mm_out<<<dim3(HID / 128, MROWS / 128), 256, SMEM_G>>>(bo, X, out);
}